// round 1
// baseline (speedup 1.0000x reference)
#include <cuda_runtime.h>
#include <cstdint>

#define SEQ   2048
#define HID   64
#define NROWS 2048
#define EPSC  1e-6f
#define WARPS_PER_BLOCK 4
#define NTHREADS (WARPS_PER_BLOCK * 32)

// Packed fp32x2 FMA (Blackwell): d.lo = a.lo*b.lo + c.lo ; d.hi likewise.
__device__ __forceinline__ unsigned long long ffma2(unsigned long long a,
                                                    unsigned long long b,
                                                    unsigned long long c) {
    unsigned long long d;
    asm("fma.rn.f32x2 %0, %1, %2, %3;" : "=l"(d) : "l"(a), "l"(b), "l"(c));
    return d;
}

__global__ void __launch_bounds__(NTHREADS)
rnn_garch_kernel(const float* __restrict__ resid,   // (2048, 2048)
                 const float* __restrict__ Wih,     // (64, 2) row-major
                 const float* __restrict__ bih,     // (64,)
                 const float* __restrict__ Whh,     // (64, 64) row-major
                 const float* __restrict__ bhh,     // (64,)
                 const float* __restrict__ fcw,     // (64,)  (shape (1,64))
                 const float* __restrict__ fcb_p,   // (1,)
                 float* __restrict__ out)           // (2048, 2048)
{
    __shared__ __align__(16) float hsh[WARPS_PER_BLOCK][2][HID];

    const int lane = threadIdx.x & 31;
    const int wid  = threadIdx.x >> 5;
    const int b    = blockIdx.x * WARPS_PER_BLOCK + wid;   // grid sized exactly

    const int j  = lane;
    const int j2 = lane + 32;

    // ---- Load W_hh rows j and j+32 into registers as packed f32x2 pairs ----
    unsigned long long W0[32], W1[32];
    {
        const ulonglong2* wr0 = reinterpret_cast<const ulonglong2*>(Whh + j  * HID);
        const ulonglong2* wr1 = reinterpret_cast<const ulonglong2*>(Whh + j2 * HID);
#pragma unroll
        for (int i = 0; i < 16; ++i) {
            ulonglong2 a = wr0[i]; W0[2 * i] = a.x; W0[2 * i + 1] = a.y;
            ulonglong2 c = wr1[i]; W1[2 * i] = c.x; W1[2 * i + 1] = c.y;
        }
    }
    const float wih_e0 = Wih[2 * j],      wih_s0 = Wih[2 * j + 1];
    const float wih_e1 = Wih[2 * j2],     wih_s1 = Wih[2 * j2 + 1];
    const float bias0  = bih[j]  + bhh[j];
    const float bias1  = bih[j2] + bhh[j2];
    const float fc0 = fcw[j], fc1 = fcw[j2];
    const float fcb = fcb_p[0];

    const float* rrow = resid + (size_t)b * SEQ;
    float*       orow = out   + (size_t)b * SEQ;

    // ---- sigma0 = unbiased variance of the row ----
    float s1 = 0.f, s2 = 0.f;
    {
        const float4* r4 = reinterpret_cast<const float4*>(rrow);
#pragma unroll 4
        for (int i = lane; i < SEQ / 4; i += 32) {
            float4 v = r4[i];
            s1 += (v.x + v.y) + (v.z + v.w);
            s2 += v.x * v.x + v.y * v.y + v.z * v.z + v.w * v.w;
        }
#pragma unroll
        for (int o = 16; o; o >>= 1) {
            s1 += __shfl_xor_sync(0xffffffffu, s1, o);
            s2 += __shfl_xor_sync(0xffffffffu, s2, o);
        }
    }
    float sigma = (s2 - s1 * s1 * (1.0f / SEQ)) * (1.0f / (SEQ - 1));

    // ---- init h buffer 0 to zeros ----
    hsh[wid][0][j]  = 0.f;
    hsh[wid][0][j2] = 0.f;
    __syncwarp();

    float sbuf = sigma;   // lane 0's slot carries sigma0 (t = 0)
    float rbuf = 0.f;

    const float* pr = &hsh[wid][0][0];
    float*       pw = &hsh[wid][1][0];

    for (int t = 1; t < SEQ; ++t) {
        const int tm1 = t - 1;
        if ((tm1 & 31) == 0) rbuf = rrow[tm1 + lane];     // coalesced refill /32 steps
        const float eps = __shfl_sync(0xffffffffu, rbuf, tm1 & 31);
        const float e2  = eps * eps;

        // input + bias contribution goes into the low half of the accumulator
        const float i0 = fmaf(e2, wih_e0, fmaf(sigma, wih_s0, bias0));
        const float i1 = fmaf(e2, wih_e1, fmaf(sigma, wih_s1, bias1));
        unsigned long long acc0 = (unsigned long long)__float_as_uint(i0); // hi = +0
        unsigned long long acc1 = (unsigned long long)__float_as_uint(i1);

        // ---- h_new = W_hh @ h : 16 LDS.128 + 64 FFMA2 ----
        const ulonglong2* hb = reinterpret_cast<const ulonglong2*>(pr);
#pragma unroll
        for (int p = 0; p < 16; ++p) {
            ulonglong2 hv = hb[p];                 // (h[4p],h[4p+1]) , (h[4p+2],h[4p+3])
            acc0 = ffma2(hv.x, W0[2 * p],     acc0);
            acc1 = ffma2(hv.x, W1[2 * p],     acc1);
            acc0 = ffma2(hv.y, W0[2 * p + 1], acc0);
            acc1 = ffma2(hv.y, W1[2 * p + 1], acc1);
        }
        const float h0 = __uint_as_float((unsigned)acc0) +
                         __uint_as_float((unsigned)(acc0 >> 32));
        const float h1 = __uint_as_float((unsigned)acc1) +
                         __uint_as_float((unsigned)(acc1 >> 32));

        // publish h_new into the other buffer (read next step)
        pw[j]  = h0;
        pw[j2] = h1;

        // ---- z = fc . h + fcb  (warp reduction) ----
        float z = fmaf(h0, fc0, h1 * fc1);
#pragma unroll
        for (int o = 16; o; o >>= 1) z += __shfl_xor_sync(0xffffffffu, z, o);
        z += fcb;

        // softplus(z) + eps   (matches jax: max(z,0) + log1p(exp(-|z|)))
        const float sp = fmaxf(z, 0.f) + log1pf(__expf(-fabsf(z)));
        sigma = sp + EPSC;

        if (lane == (t & 31)) sbuf = sigma;               // rotate into store buffer
        if ((t & 31) == 31) orow[(t & ~31) + lane] = sbuf; // coalesced 128B store
        __syncwarp();                                      // h_new visible to all lanes
        const float* tmp = pw; pw = const_cast<float*>(pr); pr = tmp;
    }
}

extern "C" void kernel_launch(void* const* d_in, const int* in_sizes, int n_in,
                              void* d_out, int out_size) {
    (void)in_sizes; (void)n_in; (void)out_size;
    const int nblocks = NROWS / WARPS_PER_BLOCK;   // 512
    rnn_garch_kernel<<<nblocks, NTHREADS>>>(
        (const float*)d_in[0],   // residuals
        (const float*)d_in[1],   // W_ih_w
        (const float*)d_in[2],   // W_ih_b
        (const float*)d_in[3],   // W_hh_w
        (const float*)d_in[4],   // W_hh_b
        (const float*)d_in[5],   // fc_w
        (const float*)d_in[6],   // fc_b
        (float*)d_out);
}

// round 2
// speedup vs baseline: 1.4671x; 1.4671x over previous
#include <cuda_runtime.h>
#include <cstdint>

#define SEQ   2048
#define HID   64
#define NROWS 2048
#define EPSC  1e-6f
#define WPB   4          // warps per block
#define NT    (WPB * 32)

// Packed fp32x2 FMA (Blackwell): d.lo = a.lo*b.lo + c.lo ; d.hi likewise.
__device__ __forceinline__ unsigned long long ffma2(unsigned long long a,
                                                    unsigned long long b,
                                                    unsigned long long c) {
    unsigned long long d;
    asm("fma.rn.f32x2 %0, %1, %2, %3;" : "=l"(d) : "l"(a), "l"(b), "l"(c));
    return d;
}
__device__ __forceinline__ float ull_sum(unsigned long long a) {
    return __uint_as_float((unsigned)a) + __uint_as_float((unsigned)(a >> 32));
}

__global__ void __launch_bounds__(NT, 2)
rnn_garch_kernel(const float* __restrict__ resid,   // (2048, 2048)
                 const float* __restrict__ Wih,     // (64, 2) row-major
                 const float* __restrict__ bih,     // (64,)
                 const float* __restrict__ Whh,     // (64, 64) row-major
                 const float* __restrict__ bhh,     // (64,)
                 const float* __restrict__ fcw,     // (64,)
                 const float* __restrict__ fcb_p,   // (1,)
                 float* __restrict__ out)           // (2048, 2048)
{
    // [warp][buffer][row-in-warp][64]
    __shared__ __align__(16) float hsh[WPB][2][2][HID];

    const int lane = threadIdx.x & 31;
    const int wid  = threadIdx.x >> 5;
    const int gw   = blockIdx.x * WPB + wid;   // global warp id, 1024 warps
    const int r0   = 2 * gw;                   // two batch rows per warp
    const int r1   = 2 * gw + 1;

    const int j  = lane;
    const int j2 = lane + 32;

    // ---- W_hh rows j and j+32 into registers as packed f32x2 pairs ----
    unsigned long long W0[32], W1[32];
    {
        const ulonglong2* wr0 = reinterpret_cast<const ulonglong2*>(Whh + j  * HID);
        const ulonglong2* wr1 = reinterpret_cast<const ulonglong2*>(Whh + j2 * HID);
#pragma unroll
        for (int i = 0; i < 16; ++i) {
            ulonglong2 a = wr0[i]; W0[2 * i] = a.x; W0[2 * i + 1] = a.y;
            ulonglong2 c = wr1[i]; W1[2 * i] = c.x; W1[2 * i + 1] = c.y;
        }
    }
    const float wih_e0 = Wih[2 * j],  wih_s0 = Wih[2 * j + 1];
    const float wih_e1 = Wih[2 * j2], wih_s1 = Wih[2 * j2 + 1];
    const float bias0  = bih[j]  + bhh[j];
    const float bias1  = bih[j2] + bhh[j2];

    // ---- z-trick constants:  z_t = g.h_{t-1} + a*e2_t + b*sig_{t-1} + c ----
    const float fcj = fcw[j], fcj2 = fcw[j2];
    float pa = fcj * wih_e0 + fcj2 * wih_e1;
    float pb = fcj * wih_s0 + fcj2 * wih_s1;
    float pc = fcj * bias0  + fcj2 * bias1;
#pragma unroll
    for (int o = 16; o; o >>= 1) {
        pa += __shfl_xor_sync(0xffffffffu, pa, o);
        pb += __shfl_xor_sync(0xffffffffu, pb, o);
        pc += __shfl_xor_sync(0xffffffffu, pc, o);
    }
    const float a_c = pa, b_c = pb, c_c = pc + fcb_p[0];

    // g = W_hh^T fc  (per-lane components g[j], g[j+32]); one-time strided loads
    float g0 = 0.f, g1 = 0.f;
#pragma unroll 8
    for (int l = 0; l < HID; ++l) {
        const float f = fcw[l];
        g0 = fmaf(f, Whh[l * HID + j],  g0);
        g1 = fmaf(f, Whh[l * HID + j2], g1);
    }

    const float* rrow0 = resid + (size_t)r0 * SEQ;
    const float* rrow1 = resid + (size_t)r1 * SEQ;
    float*       orow0 = out   + (size_t)r0 * SEQ;
    float*       orow1 = out   + (size_t)r1 * SEQ;

    // ---- sigma0 = unbiased row variance (both rows) ----
    float sig0, sig1;
    {
        float s1a = 0.f, s2a = 0.f, s1b = 0.f, s2b = 0.f;
        const float4* ra = reinterpret_cast<const float4*>(rrow0);
        const float4* rb = reinterpret_cast<const float4*>(rrow1);
#pragma unroll 4
        for (int i = lane; i < SEQ / 4; i += 32) {
            float4 v = ra[i];
            s1a += (v.x + v.y) + (v.z + v.w);
            s2a += v.x * v.x + v.y * v.y + v.z * v.z + v.w * v.w;
            float4 u = rb[i];
            s1b += (u.x + u.y) + (u.z + u.w);
            s2b += u.x * u.x + u.y * u.y + u.z * u.z + u.w * u.w;
        }
#pragma unroll
        for (int o = 16; o; o >>= 1) {
            s1a += __shfl_xor_sync(0xffffffffu, s1a, o);
            s2a += __shfl_xor_sync(0xffffffffu, s2a, o);
            s1b += __shfl_xor_sync(0xffffffffu, s1b, o);
            s2b += __shfl_xor_sync(0xffffffffu, s2b, o);
        }
        sig0 = (s2a - s1a * s1a * (1.0f / SEQ)) * (1.0f / (SEQ - 1));
        sig1 = (s2b - s1b * s1b * (1.0f / SEQ)) * (1.0f / (SEQ - 1));
    }

    // ---- init h (buffer 0) = 0 ----
    hsh[wid][0][0][j] = 0.f; hsh[wid][0][0][j2] = 0.f;
    hsh[wid][0][1][j] = 0.f; hsh[wid][0][1][j2] = 0.f;
    __syncwarp();

    float h00 = 0.f, h01 = 0.f, h10 = 0.f, h11 = 0.f;   // register copies of h_{t-1}
    float sbuf0 = sig0, sbuf1 = sig1;
    float rbuf0 = 0.f, rbuf1 = 0.f;

    const float* pr0 = &hsh[wid][0][0][0];
    const float* pr1 = &hsh[wid][0][1][0];
    float*       pw0 = &hsh[wid][1][0][0];
    float*       pw1 = &hsh[wid][1][1][0];

    for (int t = 1; t < SEQ; ++t) {
        const int tm1 = t - 1;
        const int sl  = tm1 & 31;
        if (sl == 0) { rbuf0 = rrow0[tm1 + lane]; rbuf1 = rrow1[tm1 + lane]; }
        const float eps0 = __shfl_sync(0xffffffffu, rbuf0, sl);
        const float eps1 = __shfl_sync(0xffffffffu, rbuf1, sl);
        const float e20 = eps0 * eps0;
        const float e21 = eps1 * eps1;

        // ---- z reduction straight from h_{t-1} registers (parallel with matvec) ----
        float zp0 = fmaf(g0, h00, g1 * h01);
        float zp1 = fmaf(g0, h10, g1 * h11);
#pragma unroll
        for (int o = 16; o; o >>= 1) {
            zp0 += __shfl_xor_sync(0xffffffffu, zp0, o);
            zp1 += __shfl_xor_sync(0xffffffffu, zp1, o);
        }
        const float z0 = zp0 + fmaf(a_c, e20, fmaf(b_c, sig0, c_c));
        const float z1 = zp1 + fmaf(a_c, e21, fmaf(b_c, sig1, c_c));

        // ---- input-side terms (use sig_{t-1}) ----
        const float i00 = fmaf(e20, wih_e0, fmaf(sig0, wih_s0, bias0));
        const float i01 = fmaf(e20, wih_e1, fmaf(sig0, wih_s1, bias1));
        const float i10 = fmaf(e21, wih_e0, fmaf(sig1, wih_s0, bias0));
        const float i11 = fmaf(e21, wih_e1, fmaf(sig1, wih_s1, bias1));

        // ---- matvec: 2 rows x 2 outputs x 2 chains, depth 16 each ----
        unsigned long long a00 = (unsigned long long)__float_as_uint(i00), b00 = 0ull;
        unsigned long long a01 = (unsigned long long)__float_as_uint(i01), b01 = 0ull;
        unsigned long long a10 = (unsigned long long)__float_as_uint(i10), b10 = 0ull;
        unsigned long long a11 = (unsigned long long)__float_as_uint(i11), b11 = 0ull;

        const ulonglong2* hb0 = reinterpret_cast<const ulonglong2*>(pr0);
        const ulonglong2* hb1 = reinterpret_cast<const ulonglong2*>(pr1);
#pragma unroll
        for (int p = 0; p < 16; ++p) {
            const ulonglong2 hv0 = hb0[p];
            const ulonglong2 hv1 = hb1[p];
            a00 = ffma2(hv0.x, W0[2 * p],     a00);
            b00 = ffma2(hv0.y, W0[2 * p + 1], b00);
            a01 = ffma2(hv0.x, W1[2 * p],     a01);
            b01 = ffma2(hv0.y, W1[2 * p + 1], b01);
            a10 = ffma2(hv1.x, W0[2 * p],     a10);
            b10 = ffma2(hv1.y, W0[2 * p + 1], b10);
            a11 = ffma2(hv1.x, W1[2 * p],     a11);
            b11 = ffma2(hv1.y, W1[2 * p + 1], b11);
        }
        h00 = ull_sum(a00) + ull_sum(b00);
        h01 = ull_sum(a01) + ull_sum(b01);
        h10 = ull_sum(a10) + ull_sum(b10);
        h11 = ull_sum(a11) + ull_sum(b11);

        pw0[j] = h00; pw0[j2] = h01;
        pw1[j] = h10; pw1[j2] = h11;

        // ---- sigma_t = softplus(z_t) + eps  (z computed from h_{t-1}) ----
        sig0 = fmaxf(z0, 0.f) + __logf(1.f + __expf(-fabsf(z0))) + EPSC;
        sig1 = fmaxf(z1, 0.f) + __logf(1.f + __expf(-fabsf(z1))) + EPSC;

        if (lane == sl + 1 || (sl == 31 && lane == 0)) { /* rotate below */ }
        if (lane == (t & 31)) { sbuf0 = sig0; sbuf1 = sig1; }
        if ((t & 31) == 31) {
            orow0[(t & ~31) + lane] = sbuf0;
            orow1[(t & ~31) + lane] = sbuf1;
        }
        __syncwarp();
        const float* tp0 = pw0; pw0 = const_cast<float*>(pr0); pr0 = tp0;
        const float* tp1 = pw1; pw1 = const_cast<float*>(pr1); pr1 = tp1;
    }
}

extern "C" void kernel_launch(void* const* d_in, const int* in_sizes, int n_in,
                              void* d_out, int out_size) {
    (void)in_sizes; (void)n_in; (void)out_size;
    const int nblocks = NROWS / (2 * WPB);   // 256 blocks, 2 rows per warp
    rnn_garch_kernel<<<nblocks, NT>>>(
        (const float*)d_in[0],   // residuals
        (const float*)d_in[1],   // W_ih_w
        (const float*)d_in[2],   // W_ih_b
        (const float*)d_in[3],   // W_hh_w
        (const float*)d_in[4],   // W_hh_b
        (const float*)d_in[5],   // fc_w
        (const float*)d_in[6],   // fc_b
        (float*)d_out);
}

// round 5
// speedup vs baseline: 1.6689x; 1.1376x over previous
#include <cuda_runtime.h>
#include <cstdint>

#define SEQ   2048
#define HID   64
#define NROWS 2048
#define EPSC  1e-6f
#define WPB   8          // warps per block
#define NT    (WPB * 32) // 256 threads
#define NBLK  (NROWS / (2 * WPB))   // 128 blocks -> 1 per SM, uniform

// Packed fp32x2 FMA / ADD (Blackwell)
__device__ __forceinline__ unsigned long long ffma2(unsigned long long a,
                                                    unsigned long long b,
                                                    unsigned long long c) {
    unsigned long long d;
    asm("fma.rn.f32x2 %0, %1, %2, %3;" : "=l"(d) : "l"(a), "l"(b), "l"(c));
    return d;
}
__device__ __forceinline__ unsigned long long fadd2(unsigned long long a,
                                                    unsigned long long b) {
    unsigned long long d;
    asm("add.rn.f32x2 %0, %1, %2;" : "=l"(d) : "l"(a), "l"(b));
    return d;
}
__device__ __forceinline__ float lohi(unsigned long long a) {
    return __uint_as_float((unsigned)a) + __uint_as_float((unsigned)(a >> 32));
}

struct WarpState {
    unsigned long long W0[32], W1[32];
    float wih_e0, wih_s0, wih_e1, wih_s1, bias0, bias1;
    float a_c, b_c, c_c, g0, g1;
    float h00, h01, h10, h11;       // register copy of h_{t-1} (this lane's rows)
    float sig0, sig1;
    float rbuf0, rbuf1;
    float sbuf0, sbuf1;
};

// One recurrence step: reads h_{t-1} from pr*, writes h_t into pw*.
__device__ __forceinline__ void step(WarpState& S, int t, int lane,
                                     const float* __restrict__ rrow0,
                                     const float* __restrict__ rrow1,
                                     float* __restrict__ orow0,
                                     float* __restrict__ orow1,
                                     const float* pr0, const float* pr1,
                                     float* pw0, float* pw1) {
    const int j  = lane;
    const int j2 = lane + 32;
    const int tm1 = t - 1;
    const int sl  = tm1 & 31;
    if (sl == 0) { S.rbuf0 = rrow0[tm1 + lane]; S.rbuf1 = rrow1[tm1 + lane]; }
    const float eps0 = __shfl_sync(0xffffffffu, S.rbuf0, sl);
    const float eps1 = __shfl_sync(0xffffffffu, S.rbuf1, sl);
    const float e20 = eps0 * eps0;
    const float e21 = eps1 * eps1;

    // z reduction from h_{t-1} registers — independent of the LDS matvec below,
    // its 5-deep shuffle chain overlaps the fma stream.
    float zp0 = fmaf(S.g0, S.h00, S.g1 * S.h01);
    float zp1 = fmaf(S.g0, S.h10, S.g1 * S.h11);
#pragma unroll
    for (int o = 16; o; o >>= 1) {
        zp0 += __shfl_xor_sync(0xffffffffu, zp0, o);
        zp1 += __shfl_xor_sync(0xffffffffu, zp1, o);
    }
    const float z0 = zp0 + fmaf(S.a_c, e20, fmaf(S.b_c, S.sig0, S.c_c));
    const float z1 = zp1 + fmaf(S.a_c, e21, fmaf(S.b_c, S.sig1, S.c_c));

    // input-side terms (use sig_{t-1})
    const float i00 = fmaf(e20, S.wih_e0, fmaf(S.sig0, S.wih_s0, S.bias0));
    const float i01 = fmaf(e20, S.wih_e1, fmaf(S.sig0, S.wih_s1, S.bias1));
    const float i10 = fmaf(e21, S.wih_e0, fmaf(S.sig1, S.wih_s0, S.bias0));
    const float i11 = fmaf(e21, S.wih_e1, fmaf(S.sig1, S.wih_s1, S.bias1));

    // matvec: 2 rows x 2 outputs x 2 chains (depth 16)
    unsigned long long a00 = 0ull, b00 = 0ull, a01 = 0ull, b01 = 0ull;
    unsigned long long a10 = 0ull, b10 = 0ull, a11 = 0ull, b11 = 0ull;
    const ulonglong2* hb0 = reinterpret_cast<const ulonglong2*>(pr0);
    const ulonglong2* hb1 = reinterpret_cast<const ulonglong2*>(pr1);
#pragma unroll
    for (int p = 0; p < 16; ++p) {
        const ulonglong2 hv0 = hb0[p];
        const ulonglong2 hv1 = hb1[p];
        a00 = ffma2(hv0.x, S.W0[2 * p],     a00);
        b00 = ffma2(hv0.y, S.W0[2 * p + 1], b00);
        a01 = ffma2(hv0.x, S.W1[2 * p],     a01);
        b01 = ffma2(hv0.y, S.W1[2 * p + 1], b01);
        a10 = ffma2(hv1.x, S.W0[2 * p],     a10);
        b10 = ffma2(hv1.y, S.W0[2 * p + 1], b10);
        a11 = ffma2(hv1.x, S.W1[2 * p],     a11);
        b11 = ffma2(hv1.y, S.W1[2 * p + 1], b11);
    }
    unsigned long long m;
    m = fadd2(a00, b00); S.h00 = i00 + lohi(m);
    m = fadd2(a01, b01); S.h01 = i01 + lohi(m);
    m = fadd2(a10, b10); S.h10 = i10 + lohi(m);
    m = fadd2(a11, b11); S.h11 = i11 + lohi(m);

    pw0[j] = S.h00; pw0[j2] = S.h01;
    pw1[j] = S.h10; pw1[j2] = S.h11;

    // sigma_t = softplus(z_t) + eps
    S.sig0 = fmaxf(z0, 0.f) + __logf(1.f + __expf(-fabsf(z0))) + EPSC;
    S.sig1 = fmaxf(z1, 0.f) + __logf(1.f + __expf(-fabsf(z1))) + EPSC;

    if (lane == (t & 31)) { S.sbuf0 = S.sig0; S.sbuf1 = S.sig1; }
    if ((t & 31) == 31) {
        orow0[(t & ~31) + lane] = S.sbuf0;
        orow1[(t & ~31) + lane] = S.sbuf1;
    }
    __syncwarp();
}

__global__ void __launch_bounds__(NT, 1)
rnn_garch_kernel(const float* __restrict__ resid,
                 const float* __restrict__ Wih,
                 const float* __restrict__ bih,
                 const float* __restrict__ Whh,
                 const float* __restrict__ bhh,
                 const float* __restrict__ fcw,
                 const float* __restrict__ fcb_p,
                 float* __restrict__ out) {
    __shared__ __align__(16) float hsh[WPB][2][2][HID];

    const int lane = threadIdx.x & 31;
    const int wid  = threadIdx.x >> 5;
    const int gw   = blockIdx.x * WPB + wid;
    const int r0   = 2 * gw;
    const int r1   = 2 * gw + 1;
    const int j  = lane;
    const int j2 = lane + 32;

    WarpState S;

    {
        const ulonglong2* wr0 = reinterpret_cast<const ulonglong2*>(Whh + j  * HID);
        const ulonglong2* wr1 = reinterpret_cast<const ulonglong2*>(Whh + j2 * HID);
#pragma unroll
        for (int i = 0; i < 16; ++i) {
            ulonglong2 a = wr0[i]; S.W0[2 * i] = a.x; S.W0[2 * i + 1] = a.y;
            ulonglong2 c = wr1[i]; S.W1[2 * i] = c.x; S.W1[2 * i + 1] = c.y;
        }
    }
    S.wih_e0 = Wih[2 * j];  S.wih_s0 = Wih[2 * j + 1];
    S.wih_e1 = Wih[2 * j2]; S.wih_s1 = Wih[2 * j2 + 1];
    S.bias0  = bih[j]  + bhh[j];
    S.bias1  = bih[j2] + bhh[j2];

    // z-trick constants: z_t = g.h_{t-1} + a*e2_t + b*sig_{t-1} + c
    {
        const float fcj = fcw[j], fcj2 = fcw[j2];
        float pa = fcj * S.wih_e0 + fcj2 * S.wih_e1;
        float pb = fcj * S.wih_s0 + fcj2 * S.wih_s1;
        float pc = fcj * S.bias0  + fcj2 * S.bias1;
#pragma unroll
        for (int o = 16; o; o >>= 1) {
            pa += __shfl_xor_sync(0xffffffffu, pa, o);
            pb += __shfl_xor_sync(0xffffffffu, pb, o);
            pc += __shfl_xor_sync(0xffffffffu, pc, o);
        }
        S.a_c = pa; S.b_c = pb; S.c_c = pc + fcb_p[0];
    }

    // g = W_hh^T fc
    S.g0 = 0.f; S.g1 = 0.f;
#pragma unroll 8
    for (int l = 0; l < HID; ++l) {
        const float f = fcw[l];
        S.g0 = fmaf(f, Whh[l * HID + j],  S.g0);
        S.g1 = fmaf(f, Whh[l * HID + j2], S.g1);
    }

    const float* rrow0 = resid + (size_t)r0 * SEQ;
    const float* rrow1 = resid + (size_t)r1 * SEQ;
    float*       orow0 = out   + (size_t)r0 * SEQ;
    float*       orow1 = out   + (size_t)r1 * SEQ;

    // sigma0 = unbiased row variance
    {
        float s1a = 0.f, s2a = 0.f, s1b = 0.f, s2b = 0.f;
        const float4* ra = reinterpret_cast<const float4*>(rrow0);
        const float4* rb = reinterpret_cast<const float4*>(rrow1);
#pragma unroll 4
        for (int i = lane; i < SEQ / 4; i += 32) {
            float4 v = ra[i];
            s1a += (v.x + v.y) + (v.z + v.w);
            s2a += v.x * v.x + v.y * v.y + v.z * v.z + v.w * v.w;
            float4 u = rb[i];
            s1b += (u.x + u.y) + (u.z + u.w);
            s2b += u.x * u.x + u.y * u.y + u.z * u.z + u.w * u.w;
        }
#pragma unroll
        for (int o = 16; o; o >>= 1) {
            s1a += __shfl_xor_sync(0xffffffffu, s1a, o);
            s2a += __shfl_xor_sync(0xffffffffu, s2a, o);
            s1b += __shfl_xor_sync(0xffffffffu, s1b, o);
            s2b += __shfl_xor_sync(0xffffffffu, s2b, o);
        }
        S.sig0 = (s2a - s1a * s1a * (1.0f / SEQ)) * (1.0f / (SEQ - 1));
        S.sig1 = (s2b - s1b * s1b * (1.0f / SEQ)) * (1.0f / (SEQ - 1));
    }

    hsh[wid][0][0][j] = 0.f; hsh[wid][0][0][j2] = 0.f;
    hsh[wid][0][1][j] = 0.f; hsh[wid][0][1][j2] = 0.f;
    __syncwarp();

    S.h00 = 0.f; S.h01 = 0.f; S.h10 = 0.f; S.h11 = 0.f;
    S.sbuf0 = S.sig0; S.sbuf1 = S.sig1;
    S.rbuf0 = 0.f; S.rbuf1 = 0.f;

    float* bufA0 = &hsh[wid][0][0][0];
    float* bufA1 = &hsh[wid][0][1][0];
    float* bufB0 = &hsh[wid][1][0][0];
    float* bufB1 = &hsh[wid][1][1][0];

    // t = 1 : A -> B ; then 1023 pairs (B->A, A->B) covering t = 2..2047
    step(S, 1, lane, rrow0, rrow1, orow0, orow1, bufA0, bufA1, bufB0, bufB1);
    for (int t = 2; t < SEQ; t += 2) {
        step(S, t,     lane, rrow0, rrow1, orow0, orow1, bufB0, bufB1, bufA0, bufA1);
        step(S, t + 1, lane, rrow0, rrow1, orow0, orow1, bufA0, bufA1, bufB0, bufB1);
    }
}

extern "C" void kernel_launch(void* const* d_in, const int* in_sizes, int n_in,
                              void* d_out, int out_size) {
    (void)in_sizes; (void)n_in; (void)out_size;
    rnn_garch_kernel<<<NBLK, NT>>>(
        (const float*)d_in[0],   // residuals
        (const float*)d_in[1],   // W_ih_w
        (const float*)d_in[2],   // W_ih_b
        (const float*)d_in[3],   // W_hh_w
        (const float*)d_in[4],   // W_hh_b
        (const float*)d_in[5],   // fc_w
        (const float*)d_in[6],   // fc_b
        (float*)d_out);
}

// round 9
// speedup vs baseline: 1.6805x; 1.0069x over previous
#include <cuda_runtime.h>
#include <cstdint>

#define SEQ   2048
#define HID   64
#define NROWS 2048
#define EPSC  1e-6f
#define WPB   8          // warps per block
#define NT    (WPB * 32) // 256 threads
#define NBLK  (NROWS / (2 * WPB))   // 128 blocks -> 1 per SM, uniform

// Packed fp32x2 FMA / ADD (Blackwell)
__device__ __forceinline__ unsigned long long ffma2(unsigned long long a,
                                                    unsigned long long b,
                                                    unsigned long long c) {
    unsigned long long d;
    asm("fma.rn.f32x2 %0, %1, %2, %3;" : "=l"(d) : "l"(a), "l"(b), "l"(c));
    return d;
}
__device__ __forceinline__ unsigned long long fadd2(unsigned long long a,
                                                    unsigned long long b) {
    unsigned long long d;
    asm("add.rn.f32x2 %0, %1, %2;" : "=l"(d) : "l"(a), "l"(b));
    return d;
}
__device__ __forceinline__ float flo(unsigned long long a) {
    return __uint_as_float((unsigned)a);
}
__device__ __forceinline__ float fhi(unsigned long long a) {
    return __uint_as_float((unsigned)(a >> 32));
}

struct WarpState {
    unsigned long long W0[32], W1[32];
    float wih_e0, wih_s0, wih_e1, wih_s1, bias0, bias1;
    float a_c, b_c, c_c, g0, g1;
    float h00, h01, h10, h11;       // register copy of h_{t-1} (this lane's rows)
    float sig0, sig1;
    float rbuf0, rbuf1;             // current 32-step eps group
    float rnext0, rnext1;           // prefetched next group
    float sbuf0, sbuf1;
};

// One recurrence step. Spine: LDS -> ffma -> merge -> STS -> SYNC.
// Tail (softplus/sigma/output) sits AFTER the sync so it overlaps the next
// step's LDS/ffma stream (no barrier in between).
__device__ __forceinline__ void step(WarpState& S, int t, int lane,
                                     const float* __restrict__ rrow0,
                                     const float* __restrict__ rrow1,
                                     float* __restrict__ orow0,
                                     float* __restrict__ orow1,
                                     const float* pr0, const float* pr1,
                                     float* pw0, float* pw1) {
    const int j  = lane;
    const int j2 = lane + 32;
    const int tm1 = t - 1;
    const int sl  = tm1 & 31;

    if (sl == 0) { S.rbuf0 = S.rnext0; S.rbuf1 = S.rnext1; }
    const float eps0 = __shfl_sync(0xffffffffu, S.rbuf0, sl);
    const float eps1 = __shfl_sync(0xffffffffu, S.rbuf1, sl);
    if (sl == 16) {                       // prefetch next group, 16 steps early
        const int base = (tm1 & ~31) + 32;
        if (base < SEQ) {
            S.rnext0 = rrow0[base + lane];
            S.rnext1 = rrow1[base + lane];
        }
    }
    const float e20 = eps0 * eps0;
    const float e21 = eps1 * eps1;

    // ---- matvec: 2 rows x 2 outputs x 2 chains (depth 16) — the spine ----
    unsigned long long a00 = 0ull, b00 = 0ull, a01 = 0ull, b01 = 0ull;
    unsigned long long a10 = 0ull, b10 = 0ull, a11 = 0ull, b11 = 0ull;
    const ulonglong2* hb0 = reinterpret_cast<const ulonglong2*>(pr0);
    const ulonglong2* hb1 = reinterpret_cast<const ulonglong2*>(pr1);
#pragma unroll
    for (int p = 0; p < 16; ++p) {
        const ulonglong2 hv0 = hb0[p];
        const ulonglong2 hv1 = hb1[p];
        a00 = ffma2(hv0.x, S.W0[2 * p],     a00);
        b00 = ffma2(hv0.y, S.W0[2 * p + 1], b00);
        a01 = ffma2(hv0.x, S.W1[2 * p],     a01);
        b01 = ffma2(hv0.y, S.W1[2 * p + 1], b01);
        a10 = ffma2(hv1.x, S.W0[2 * p],     a10);
        b10 = ffma2(hv1.y, S.W0[2 * p + 1], b10);
        a11 = ffma2(hv1.x, S.W1[2 * p],     a11);
        b11 = ffma2(hv1.y, S.W1[2 * p + 1], b11);
    }

    // z shuffle-reduce from h_{t-1} registers — off the spine, overlaps ffma
    float zp0 = fmaf(S.g0, S.h00, S.g1 * S.h01);
    float zp1 = fmaf(S.g0, S.h10, S.g1 * S.h11);
#pragma unroll
    for (int o = 16; o; o >>= 1) {
        zp0 += __shfl_xor_sync(0xffffffffu, zp0, o);
        zp1 += __shfl_xor_sync(0xffffffffu, zp1, o);
    }

    // input-side terms (use sig_{t-1}, produced in previous step's tail)
    const float i00 = fmaf(e20, S.wih_e0, fmaf(S.sig0, S.wih_s0, S.bias0));
    const float i01 = fmaf(e20, S.wih_e1, fmaf(S.sig0, S.wih_s1, S.bias1));
    const float i10 = fmaf(e21, S.wih_e0, fmaf(S.sig1, S.wih_s0, S.bias0));
    const float i11 = fmaf(e21, S.wih_e1, fmaf(S.sig1, S.wih_s1, S.bias1));

    // merge and publish h_t
    unsigned long long m;
    m = fadd2(a00, b00); S.h00 = (i00 + flo(m)) + fhi(m);
    m = fadd2(a01, b01); S.h01 = (i01 + flo(m)) + fhi(m);
    m = fadd2(a10, b10); S.h10 = (i10 + flo(m)) + fhi(m);
    m = fadd2(a11, b11); S.h11 = (i11 + flo(m)) + fhi(m);

    pw0[j] = S.h00; pw0[j2] = S.h01;
    pw1[j] = S.h10; pw1[j2] = S.h11;
    __syncwarp();

    // ---- tail: AFTER the sync -> overlaps next step's LDS/ffma ----
    const float z0 = zp0 + fmaf(S.a_c, e20, fmaf(S.b_c, S.sig0, S.c_c));
    const float z1 = zp1 + fmaf(S.a_c, e21, fmaf(S.b_c, S.sig1, S.c_c));
    S.sig0 = fmaxf(z0, 0.f) + __logf(1.f + __expf(-fabsf(z0))) + EPSC;
    S.sig1 = fmaxf(z1, 0.f) + __logf(1.f + __expf(-fabsf(z1))) + EPSC;

    if (lane == (t & 31)) { S.sbuf0 = S.sig0; S.sbuf1 = S.sig1; }
    if ((t & 31) == 31) {
        orow0[(t & ~31) + lane] = S.sbuf0;
        orow1[(t & ~31) + lane] = S.sbuf1;
    }
}

__global__ void __launch_bounds__(NT, 1)
rnn_garch_kernel(const float* __restrict__ resid,
                 const float* __restrict__ Wih,
                 const float* __restrict__ bih,
                 const float* __restrict__ Whh,
                 const float* __restrict__ bhh,
                 const float* __restrict__ fcw,
                 const float* __restrict__ fcb_p,
                 float* __restrict__ out) {
    __shared__ __align__(16) float hsh[WPB][2][2][HID];

    const int lane = threadIdx.x & 31;
    const int wid  = threadIdx.x >> 5;
    const int gw   = blockIdx.x * WPB + wid;
    const int r0   = 2 * gw;
    const int r1   = 2 * gw + 1;
    const int j  = lane;
    const int j2 = lane + 32;

    WarpState S;

    {
        const ulonglong2* wr0 = reinterpret_cast<const ulonglong2*>(Whh + j  * HID);
        const ulonglong2* wr1 = reinterpret_cast<const ulonglong2*>(Whh + j2 * HID);
#pragma unroll
        for (int i = 0; i < 16; ++i) {
            ulonglong2 a = wr0[i]; S.W0[2 * i] = a.x; S.W0[2 * i + 1] = a.y;
            ulonglong2 c = wr1[i]; S.W1[2 * i] = c.x; S.W1[2 * i + 1] = c.y;
        }
    }
    S.wih_e0 = Wih[2 * j];  S.wih_s0 = Wih[2 * j + 1];
    S.wih_e1 = Wih[2 * j2]; S.wih_s1 = Wih[2 * j2 + 1];
    S.bias0  = bih[j]  + bhh[j];
    S.bias1  = bih[j2] + bhh[j2];

    // z-trick constants: z_t = g.h_{t-1} + a*e2_t + b*sig_{t-1} + c
    {
        const float fcj = fcw[j], fcj2 = fcw[j2];
        float pa = fcj * S.wih_e0 + fcj2 * S.wih_e1;
        float pb = fcj * S.wih_s0 + fcj2 * S.wih_s1;
        float pc = fcj * S.bias0  + fcj2 * S.bias1;
#pragma unroll
        for (int o = 16; o; o >>= 1) {
            pa += __shfl_xor_sync(0xffffffffu, pa, o);
            pb += __shfl_xor_sync(0xffffffffu, pb, o);
            pc += __shfl_xor_sync(0xffffffffu, pc, o);
        }
        S.a_c = pa; S.b_c = pb; S.c_c = pc + fcb_p[0];
    }

    // g = W_hh^T fc
    S.g0 = 0.f; S.g1 = 0.f;
#pragma unroll 8
    for (int l = 0; l < HID; ++l) {
        const float f = fcw[l];
        S.g0 = fmaf(f, Whh[l * HID + j],  S.g0);
        S.g1 = fmaf(f, Whh[l * HID + j2], S.g1);
    }

    const float* rrow0 = resid + (size_t)r0 * SEQ;
    const float* rrow1 = resid + (size_t)r1 * SEQ;
    float*       orow0 = out   + (size_t)r0 * SEQ;
    float*       orow1 = out   + (size_t)r1 * SEQ;

    // sigma0 = unbiased row variance
    {
        float s1a = 0.f, s2a = 0.f, s1b = 0.f, s2b = 0.f;
        const float4* ra = reinterpret_cast<const float4*>(rrow0);
        const float4* rb = reinterpret_cast<const float4*>(rrow1);
#pragma unroll 4
        for (int i = lane; i < SEQ / 4; i += 32) {
            float4 v = ra[i];
            s1a += (v.x + v.y) + (v.z + v.w);
            s2a += v.x * v.x + v.y * v.y + v.z * v.z + v.w * v.w;
            float4 u = rb[i];
            s1b += (u.x + u.y) + (u.z + u.w);
            s2b += u.x * u.x + u.y * u.y + u.z * u.z + u.w * u.w;
        }
#pragma unroll
        for (int o = 16; o; o >>= 1) {
            s1a += __shfl_xor_sync(0xffffffffu, s1a, o);
            s2a += __shfl_xor_sync(0xffffffffu, s2a, o);
            s1b += __shfl_xor_sync(0xffffffffu, s1b, o);
            s2b += __shfl_xor_sync(0xffffffffu, s2b, o);
        }
        S.sig0 = (s2a - s1a * s1a * (1.0f / SEQ)) * (1.0f / (SEQ - 1));
        S.sig1 = (s2b - s1b * s1b * (1.0f / SEQ)) * (1.0f / (SEQ - 1));
    }

    hsh[wid][0][0][j] = 0.f; hsh[wid][0][0][j2] = 0.f;
    hsh[wid][0][1][j] = 0.f; hsh[wid][0][1][j2] = 0.f;
    __syncwarp();

    S.h00 = 0.f; S.h01 = 0.f; S.h10 = 0.f; S.h11 = 0.f;
    S.sbuf0 = S.sig0; S.sbuf1 = S.sig1;
    S.rbuf0 = 0.f; S.rbuf1 = 0.f;
    S.rnext0 = rrow0[lane];            // group 0 prefetch
    S.rnext1 = rrow1[lane];

    float* bufA0 = &hsh[wid][0][0][0];
    float* bufA1 = &hsh[wid][0][1][0];
    float* bufB0 = &hsh[wid][1][0][0];
    float* bufB1 = &hsh[wid][1][1][0];

    // t = 1 : A -> B ; then 1023 pairs (B->A, A->B)
    step(S, 1, lane, rrow0, rrow1, orow0, orow1, bufA0, bufA1, bufB0, bufB1);
    for (int t = 2; t < SEQ; t += 2) {
        step(S, t,     lane, rrow0, rrow1, orow0, orow1, bufB0, bufB1, bufA0, bufA1);
        step(S, t + 1, lane, rrow0, rrow1, orow0, orow1, bufA0, bufA1, bufB0, bufB1);
    }
}

extern "C" void kernel_launch(void* const* d_in, const int* in_sizes, int n_in,
                              void* d_out, int out_size) {
    (void)in_sizes; (void)n_in; (void)out_size;
    rnn_garch_kernel<<<NBLK, NT>>>(
        (const float*)d_in[0],   // residuals
        (const float*)d_in[1],   // W_ih_w
        (const float*)d_in[2],   // W_ih_b
        (const float*)d_in[3],   // W_hh_w
        (const float*)d_in[4],   // W_hh_b
        (const float*)d_in[5],   // fc_w
        (const float*)d_in[6],   // fc_b
        (float*)d_out);
}